// round 1
// baseline (speedup 1.0000x reference)
#include <cuda_runtime.h>
#include <stdint.h>

// Problem dims (fixed by the reference): out [B, C, X, Y] fp32
#define BB 4
#define CC 256
#define XX 256
#define YY 256

// Inverse index: dense cell (b,x,y) -> feature row n, or -1 if empty. 1 MB.
__device__ int d_inv[BB * XX * YY];

// ---------------------------------------------------------------------------
// Kernel 1: fill inverse index with -1 (vectorized int4 stores).
// total ints = 262144 -> 65536 int4 -> 256 blocks x 256 threads
// ---------------------------------------------------------------------------
__global__ void init_inv_kernel() {
    int i = blockIdx.x * blockDim.x + threadIdx.x;
    reinterpret_cast<int4*>(d_inv)[i] = make_int4(-1, -1, -1, -1);
}

// ---------------------------------------------------------------------------
// Kernel 2: scatter row index n into d_inv at its (b,x,y). Bounds-guarded
// to match jnp scatter mode="drop".
// ---------------------------------------------------------------------------
__global__ void build_inv_kernel(const int* __restrict__ coords, int n) {
    int i = blockIdx.x * blockDim.x + threadIdx.x;
    if (i >= n) return;
    int b = coords[3 * i + 0];
    int x = coords[3 * i + 1];
    int y = coords[3 * i + 2];
    if ((unsigned)b < BB && (unsigned)x < XX && (unsigned)y < YY) {
        d_inv[(b * XX + x) * YY + y] = i;
    }
}

// ---------------------------------------------------------------------------
// Kernel 3: sector-complete gather.
// One block per 8 consecutive y-cells of one (b, x) row. 512 threads:
//   c = tid >> 1 (0..255), k = (tid & 1) * 4 (first/second half of the sector)
// Each thread gathers 4 feature values (rows inv[L+k..L+k+3], channel c)
// and writes one float4 -> each 32B output sector is written exactly once,
// fully, by a pair of adjacent threads. Empty cells write 0.0f, so this also
// performs the zero-initialization of the poisoned output.
// ---------------------------------------------------------------------------
__global__ void __launch_bounds__(512, 4)
gather_kernel(const float* __restrict__ feats, float* __restrict__ out) {
    const int L   = blockIdx.x * 8;          // linear cell index of group base
    const int b   = L / (XX * YY);
    const int rem = L % (XX * YY);
    const int x   = rem / YY;
    const int yb  = rem % YY;                 // group-aligned (YY % 8 == 0)

    const int tid = threadIdx.x;              // 0..511
    const int c   = tid >> 1;                 // 0..255
    const int k   = (tid & 1) << 2;           // 0 or 4

    const int* __restrict__ inv = d_inv + L + k;
    const int r0 = __ldg(inv + 0);
    const int r1 = __ldg(inv + 1);
    const int r2 = __ldg(inv + 2);
    const int r3 = __ldg(inv + 3);

    float4 v;
    v.x = (r0 >= 0) ? __ldg(feats + (size_t)r0 * CC + c) : 0.0f;
    v.y = (r1 >= 0) ? __ldg(feats + (size_t)r1 * CC + c) : 0.0f;
    v.z = (r2 >= 0) ? __ldg(feats + (size_t)r2 * CC + c) : 0.0f;
    v.w = (r3 >= 0) ? __ldg(feats + (size_t)r3 * CC + c) : 0.0f;

    const size_t o = ((((size_t)b * CC + c) * XX + x) * YY) + yb + k;
    *reinterpret_cast<float4*>(out + o) = v;
}

// ---------------------------------------------------------------------------
// Launcher
// ---------------------------------------------------------------------------
extern "C" void kernel_launch(void* const* d_in, const int* in_sizes, int n_in,
                              void* d_out, int out_size) {
    const float* feats  = (const float*)d_in[0];
    const int*   coords = (const int*)d_in[1];
    float*       out    = (float*)d_out;

    const int n = in_sizes[1] / 3;  // number of sparse points

    // 1) inv = -1
    init_inv_kernel<<<(BB * XX * YY / 4) / 256, 256>>>();

    // 2) scatter row indices
    build_inv_kernel<<<(n + 255) / 256, 256>>>(coords, n);

    // 3) dense gather (writes every output element exactly once)
    gather_kernel<<<(BB * XX * YY) / 8, 512>>>(feats, out);
}

// round 3
// speedup vs baseline: 1.0346x; 1.0346x over previous
#include <cuda_runtime.h>
#include <stdint.h>

// Output: [B, C, X, Y] fp32
#define BB 4
#define CC 256
#define XX 256
#define YY 256

// Inverse index: dense cell (b,x,y) -> (feature row + 1), 0 = empty. 1 MB.
// __device__ globals are zero-initialized at module load; gather_kernel
// resets every entry it reads back to 0 before it exits, so every launch
// (correctness run, capture, each graph replay) starts from all-zero state.
__device__ int d_inv[BB * XX * YY];

// ---------------------------------------------------------------------------
// Kernel 1: scatter (row index + 1) into d_inv. Bounds-guarded = mode="drop".
// ---------------------------------------------------------------------------
__global__ void build_inv_kernel(const int* __restrict__ coords, int n) {
    int i = blockIdx.x * blockDim.x + threadIdx.x;
    if (i >= n) return;
    int b = coords[3 * i + 0];
    int x = coords[3 * i + 1];
    int y = coords[3 * i + 2];
    if ((unsigned)b < BB && (unsigned)x < XX && (unsigned)y < YY) {
        d_inv[(b * XX + x) * YY + y] = i + 1;
    }
}

// ---------------------------------------------------------------------------
// Kernel 2: transpose-tile gather, XOR-swizzled smem (no padding, no
// misalignment, conflict-free in BOTH phases).
//
// One block = 32 consecutive y cells of one (b, x) row, all 256 channels.
// Tile: flat float[256*32] (32 KB); logical element (c, j) lives at
//   tile[c*32 + (j ^ ((c>>2) & 31))]
//
// Load phase: thread (jb, sub): LDG.128 feats[row s_inv[j]-1, 4*sub..4*sub+3],
//   4x STS.32 to rows 4*sub+e, column j^(sub&31). Within a warp j is fixed
//   and sub&31 spans 0..31 -> 32 distinct banks: conflict-free.
// Store phase: warp w owns channels w*32..w*32+31; lane l reads (c, l) at
//   column l^((c>>2)&31) -> bank l^const: conflict-free. STG.32 with 32
//   contiguous lanes = one full 128B output line per store (optimal).
//
// Every output element is written exactly once (zeros for empty cells), so
// the poisoned output is fully initialized here.
// ---------------------------------------------------------------------------
__global__ void __launch_bounds__(256, 4)
gather_kernel(const float* __restrict__ feats, float* __restrict__ out) {
    __shared__ int   s_inv[32];
    __shared__ float tile[CC * 32];

    const int L  = blockIdx.x * 32;      // base linear cell index
    const int b  = L >> 16;              // / (XX*YY)
    const int x  = (L >> 8) & 255;       // / YY % XX
    const int yb = L & 255;              // % YY (multiple of 32)

    const int tid = threadIdx.x;

    // Stage inverse indices; reset to 0 so the next launch starts clean.
    if (tid < 32) {
        int v = d_inv[L + tid];
        s_inv[tid] = v;
        d_inv[L + tid] = 0;
    }
    __syncthreads();

    // ---- load phase: 4 y-rows per pass, 8 passes ----
    const int sub = tid & 63;            // float4 index within 256-ch row
    const int jb  = tid >> 6;            // 0..3
    const int sw  = sub & 31;            // swizzle key for this thread's cols
    #pragma unroll
    for (int jj = 0; jj < 32; jj += 4) {
        const int j = jj + jb;
        const int r = s_inv[j];
        float4 v = make_float4(0.f, 0.f, 0.f, 0.f);
        if (r) {
            v = *reinterpret_cast<const float4*>(
                    feats + (size_t)(r - 1) * CC + (sub << 2));
        }
        const int col = j ^ sw;
        tile[((sub << 2) + 0) * 32 + col] = v.x;
        tile[((sub << 2) + 1) * 32 + col] = v.y;
        tile[((sub << 2) + 2) * 32 + col] = v.z;
        tile[((sub << 2) + 3) * 32 + col] = v.w;
    }
    __syncthreads();

    // ---- store phase: full 128 B output lines ----
    const int warp = tid >> 5;
    const int lane = tid & 31;
    float* outp = out + ((size_t)b * CC) * (XX * YY) + (size_t)x * YY + yb + lane;
    #pragma unroll
    for (int ci = 0; ci < 32; ci++) {
        const int c   = (warp << 5) + ci;
        const int col = lane ^ ((c >> 2) & 31);
        outp[(size_t)c * (XX * YY)] = tile[c * 32 + col];
    }
}

// ---------------------------------------------------------------------------
// Launcher
// ---------------------------------------------------------------------------
extern "C" void kernel_launch(void* const* d_in, const int* in_sizes, int n_in,
                              void* d_out, int out_size) {
    const float* feats  = (const float*)d_in[0];
    const int*   coords = (const int*)d_in[1];
    float*       out    = (float*)d_out;

    const int n = in_sizes[1] / 3;  // number of sparse points

    build_inv_kernel<<<(n + 255) / 256, 256>>>(coords, n);
    gather_kernel<<<(BB * XX * YY) / 32, 256>>>(feats, out);
}